// round 16
// baseline (speedup 1.0000x reference)
#include <cuda_runtime.h>
#include <math.h>

#define BATCH 2
#define SEQ   2048
#define EMB   512
#define NH    8
#define HD    64
#define BS    (BATCH*SEQ)      /* 4096 */
#define W1LD  (EMB+NH)         /* 520  */
#define NJT   (SEQ/128)        /* 16 j-tiles */

// ---------------- scratch (device globals; no allocation allowed) ----------------
__device__ float g_q[BS*EMB];
__device__ float g_k[BS*EMB];
__device__ float g_v[BS*EMB];
__device__ float g_ewm[(size_t)BATCH*SEQ*SEQ];         // mean edge weights (32 MB)
__device__ float g_zpart[(size_t)BATCH*NJT*NH*SEQ];    // per-jtile softmax partials
__device__ float g_zinv[(size_t)BATCH*NH*SEQ];         // 1/(8*Z)
__device__ int   g_cnt[BS];
__device__ float g_invnn[BS];
__device__ float g_mid[BS*EMB];
__device__ float g_pre[BS*EMB];
__device__ float g_msg[BS*EMB];
__device__ float g_bm1eff[EMB];

// ---------------- fast exp of (0.125*x) on the FMA pipe --------------------------
__device__ __forceinline__ float fast_exp_s(float x) {
    float t  = x * (1.4426950408889634f * 0.125f);   // scale folded into log2(e)
    t = fmaxf(t, -115.0f);
    float fi = floorf(t + 0.5f);
    float f  = t - fi;
    float u  = f * 0.6931471805599453f;
    float p = 1.0f + u*(1.0f + u*(0.5f + u*(0.16666667f + u*(0.041666667f + u*0.0083333333f))));
    return __int_as_float(((int)fi + 127) << 23) * p;
}

// ================= shared GEMM body: 128x128 tile, BK=16, split 4+4 microtile ====
template<bool TB, bool GELU>
__device__ __forceinline__ void gemm_body(
    const float* __restrict__ A, const float* __restrict__ B,
    const float* __restrict__ bias, const float* __restrict__ res,
    float* __restrict__ C, int K, int lda, int ldb, int ldc,
    int m0, int n0, float alpha)
{
    __shared__ __align__(16) float As[2][16][132];
    __shared__ __align__(16) float Bs[2][16][132];

    const int tid = threadIdx.x;
    const int tx = tid & 15;
    const int ty = tid >> 4;

    const int aRow = tid >> 2;
    const int aK4  = (tid & 3) << 2;
    const int bK   = tid >> 5;
    const int bN4  = (tid & 31) << 2;

    float4 a0, a1, b0, b1;

    {
        const float* Ap = A + (long long)m0 * lda;
        a0 = *(const float4*)&Ap[(long long)aRow        * lda + aK4];
        a1 = *(const float4*)&Ap[(long long)(aRow + 64) * lda + aK4];
        if (TB) {
            const float* Bp = B + (long long)n0 * ldb;
            b0 = *(const float4*)&Bp[(long long)aRow        * ldb + aK4];
            b1 = *(const float4*)&Bp[(long long)(aRow + 64) * ldb + aK4];
        } else {
            const float* Bp = B + n0;
            b0 = *(const float4*)&Bp[(long long)bK       * ldb + bN4];
            b1 = *(const float4*)&Bp[(long long)(bK + 8) * ldb + bN4];
        }
    }
    {
        As[0][aK4+0][aRow] = a0.x; As[0][aK4+1][aRow] = a0.y;
        As[0][aK4+2][aRow] = a0.z; As[0][aK4+3][aRow] = a0.w;
        As[0][aK4+0][aRow+64] = a1.x; As[0][aK4+1][aRow+64] = a1.y;
        As[0][aK4+2][aRow+64] = a1.z; As[0][aK4+3][aRow+64] = a1.w;
        if (TB) {
            Bs[0][aK4+0][aRow] = b0.x; Bs[0][aK4+1][aRow] = b0.y;
            Bs[0][aK4+2][aRow] = b0.z; Bs[0][aK4+3][aRow] = b0.w;
            Bs[0][aK4+0][aRow+64] = b1.x; Bs[0][aK4+1][aRow+64] = b1.y;
            Bs[0][aK4+2][aRow+64] = b1.z; Bs[0][aK4+3][aRow+64] = b1.w;
        } else {
            *(float4*)&Bs[0][bK    ][bN4] = b0;
            *(float4*)&Bs[0][bK + 8][bN4] = b1;
        }
    }
    __syncthreads();

    float acc[8][8];
#pragma unroll
    for (int i = 0; i < 8; i++)
#pragma unroll
        for (int j = 0; j < 8; j++) acc[i][j] = 0.0f;

    int buf = 0;
    for (int k0 = 0; k0 < K; k0 += 16) {
        const int k1 = k0 + 16;
        const bool more = (k1 < K);
        if (more) {
            const float* Ap = A + (long long)m0 * lda + k1;
            a0 = *(const float4*)&Ap[(long long)aRow        * lda + aK4];
            a1 = *(const float4*)&Ap[(long long)(aRow + 64) * lda + aK4];
            if (TB) {
                const float* Bp = B + (long long)n0 * ldb + k1;
                b0 = *(const float4*)&Bp[(long long)aRow        * ldb + aK4];
                b1 = *(const float4*)&Bp[(long long)(aRow + 64) * ldb + aK4];
            } else {
                const float* Bp = B + (long long)k1 * ldb + n0;
                b0 = *(const float4*)&Bp[(long long)bK       * ldb + bN4];
                b1 = *(const float4*)&Bp[(long long)(bK + 8) * ldb + bN4];
            }
        }

#pragma unroll
        for (int kk = 0; kk < 16; kk++) {
            float af[8], bf[8];
            *(float4*)&af[0] = *(const float4*)&As[buf][kk][ty * 4];
            *(float4*)&af[4] = *(const float4*)&As[buf][kk][ty * 4 + 64];
            *(float4*)&bf[0] = *(const float4*)&Bs[buf][kk][tx * 4];
            *(float4*)&bf[4] = *(const float4*)&Bs[buf][kk][tx * 4 + 64];
#pragma unroll
            for (int i = 0; i < 8; i++)
#pragma unroll
                for (int j = 0; j < 8; j++)
                    acc[i][j] = fmaf(af[i], bf[j], acc[i][j]);
        }

        if (more) {
            const int nb = buf ^ 1;
            As[nb][aK4+0][aRow] = a0.x; As[nb][aK4+1][aRow] = a0.y;
            As[nb][aK4+2][aRow] = a0.z; As[nb][aK4+3][aRow] = a0.w;
            As[nb][aK4+0][aRow+64] = a1.x; As[nb][aK4+1][aRow+64] = a1.y;
            As[nb][aK4+2][aRow+64] = a1.z; As[nb][aK4+3][aRow+64] = a1.w;
            if (TB) {
                Bs[nb][aK4+0][aRow] = b0.x; Bs[nb][aK4+1][aRow] = b0.y;
                Bs[nb][aK4+2][aRow] = b0.z; Bs[nb][aK4+3][aRow] = b0.w;
                Bs[nb][aK4+0][aRow+64] = b1.x; Bs[nb][aK4+1][aRow+64] = b1.y;
                Bs[nb][aK4+2][aRow+64] = b1.z; Bs[nb][aK4+3][aRow+64] = b1.w;
            } else {
                *(float4*)&Bs[nb][bK    ][bN4] = b0;
                *(float4*)&Bs[nb][bK + 8][bN4] = b1;
            }
            __syncthreads();
            buf = nb;
        }
    }

    float bb0[4], bb1[4];
#pragma unroll
    for (int j = 0; j < 4; j++) {
        bb0[j] = bias ? bias[n0 + tx * 4 + j]      : 0.0f;
        bb1[j] = bias ? bias[n0 + 64 + tx * 4 + j] : 0.0f;
    }

#pragma unroll
    for (int ih = 0; ih < 2; ih++) {
#pragma unroll
        for (int i = 0; i < 4; i++) {
            const long long m = m0 + ih * 64 + ty * 4 + i;
            const int ia = ih * 4 + i;
            float o0[4], o1[4];
#pragma unroll
            for (int j = 0; j < 4; j++) {
                float v0 = fmaf(acc[ia][j],     alpha, bb0[j]);
                float v1 = fmaf(acc[ia][j + 4], alpha, bb1[j]);
                if (GELU) {
                    v0 = 0.5f * v0 * (1.0f + erff(v0 * 0.70710678118654752f));
                    v1 = 0.5f * v1 * (1.0f + erff(v1 * 0.70710678118654752f));
                }
                o0[j] = v0; o1[j] = v1;
            }
            if (res) {
                float4 r0 = *(const float4*)&res[m * ldc + n0 + tx * 4];
                float4 r1 = *(const float4*)&res[m * ldc + n0 + 64 + tx * 4];
                o0[0] += r0.x; o0[1] += r0.y; o0[2] += r0.z; o0[3] += r0.w;
                o1[0] += r1.x; o1[1] += r1.y; o1[2] += r1.z; o1[3] += r1.w;
            }
            *(float4*)&C[m * ldc + n0 + tx * 4     ] = *(float4*)&o0[0];
            *(float4*)&C[m * ldc + n0 + 64 + tx * 4] = *(float4*)&o1[0];
        }
    }
}

template<bool TB, bool GELU>
__global__ __launch_bounds__(256)
void sgemm128(const float* __restrict__ A, const float* __restrict__ B,
              const float* __restrict__ bias, const float* __restrict__ res,
              float* __restrict__ C,
              int K, int lda, int ldb, int ldc,
              long long sA, long long sB, long long sC, float alpha)
{
    gemm_body<TB, GELU>(A + (long long)blockIdx.z * sA,
                        B + (long long)blockIdx.z * sB,
                        bias, res ? res + (long long)blockIdx.z * sC : nullptr,
                        C + (long long)blockIdx.z * sC,
                        K, lda, ldb, ldc,
                        blockIdx.y * 128, blockIdx.x * 128, alpha);
}

// ---- fused QKV ----
__global__ __launch_bounds__(256)
void qkv_gemm(const float* __restrict__ x,
              const float* __restrict__ Wq, const float* __restrict__ bq,
              const float* __restrict__ Wk, const float* __restrict__ bk,
              const float* __restrict__ Wv, const float* __restrict__ bv,
              float* __restrict__ q, float* __restrict__ k, float* __restrict__ v)
{
    const int seg = blockIdx.x >> 2;
    const float* W = (seg == 0) ? Wq : (seg == 1) ? Wk : Wv;
    const float* b = (seg == 0) ? bq : (seg == 1) ? bk : bv;
    float*     out = (seg == 0) ? q  : (seg == 1) ? k  : v;
    gemm_body<true, false>(x, W, b, nullptr, out,
                           EMB, EMB, EMB, EMB,
                           blockIdx.y * 128, (blockIdx.x & 3) * 128, 1.0f);
}

// ===== fused scores GEMM skeleton shared by z_kernel / ewm_kernel =================
// A=q (rows i), B=k (rows j), K=512 with per-head (64-col) flushes.
// PHASE 0: accumulate Z partials. PHASE 1: emit ewm + neighbor counts.
template<int PHASE>
__global__ __launch_bounds__(256)
void score_pass(const float* __restrict__ Q, const float* __restrict__ Km,
                float* __restrict__ zpart,          // PHASE 0 out
                const float* __restrict__ zinv,     // PHASE 1 in
                float* __restrict__ ewm, int* __restrict__ cnt)  // PHASE 1 out
{
    __shared__ __align__(16) float As[2][16][132];
    __shared__ __align__(16) float Bs[2][16][132];
    __shared__ float zsm[NH][128];                  // PHASE 0 flush target

    const int z  = blockIdx.z;                      // batch
    const int jt = blockIdx.x;                      // j tile
    const float* A = Q  + (long long)z * SEQ * EMB;
    const float* B = Km + (long long)z * SEQ * EMB;
    const int m0 = blockIdx.y * 128;
    const int n0 = jt * 128;

    const int tid = threadIdx.x;
    const int tx = tid & 15;
    const int ty = tid >> 4;
    const int aRow = tid >> 2;
    const int aK4  = (tid & 3) << 2;

    float4 a0, a1, b0, b1;
    // prologue k=0
    {
        const float* Ap = A + (long long)m0 * EMB;
        const float* Bp = B + (long long)n0 * EMB;
        a0 = *(const float4*)&Ap[(long long)aRow        * EMB + aK4];
        a1 = *(const float4*)&Ap[(long long)(aRow + 64) * EMB + aK4];
        b0 = *(const float4*)&Bp[(long long)aRow        * EMB + aK4];
        b1 = *(const float4*)&Bp[(long long)(aRow + 64) * EMB + aK4];
        As[0][aK4+0][aRow] = a0.x; As[0][aK4+1][aRow] = a0.y;
        As[0][aK4+2][aRow] = a0.z; As[0][aK4+3][aRow] = a0.w;
        As[0][aK4+0][aRow+64] = a1.x; As[0][aK4+1][aRow+64] = a1.y;
        As[0][aK4+2][aRow+64] = a1.z; As[0][aK4+3][aRow+64] = a1.w;
        Bs[0][aK4+0][aRow] = b0.x; Bs[0][aK4+1][aRow] = b0.y;
        Bs[0][aK4+2][aRow] = b0.z; Bs[0][aK4+3][aRow] = b0.w;
        Bs[0][aK4+0][aRow+64] = b1.x; Bs[0][aK4+1][aRow+64] = b1.y;
        Bs[0][aK4+2][aRow+64] = b1.z; Bs[0][aK4+3][aRow+64] = b1.w;
    }
    __syncthreads();

    float acc[8][8], ew[8][8];
#pragma unroll
    for (int i = 0; i < 8; i++)
#pragma unroll
        for (int j = 0; j < 8; j++) { acc[i][j] = 0.0f; ew[i][j] = 0.0f; }

    int buf = 0;
    for (int ks = 0; ks < 32; ks++) {
        const int k1 = (ks + 1) * 16;
        const bool more = (k1 < EMB);
        if (more) {
            const float* Ap = A + (long long)m0 * EMB + k1;
            const float* Bp = B + (long long)n0 * EMB + k1;
            a0 = *(const float4*)&Ap[(long long)aRow        * EMB + aK4];
            a1 = *(const float4*)&Ap[(long long)(aRow + 64) * EMB + aK4];
            b0 = *(const float4*)&Bp[(long long)aRow        * EMB + aK4];
            b1 = *(const float4*)&Bp[(long long)(aRow + 64) * EMB + aK4];
        }

#pragma unroll
        for (int kk = 0; kk < 16; kk++) {
            float af[8], bf[8];
            *(float4*)&af[0] = *(const float4*)&As[buf][kk][ty * 4];
            *(float4*)&af[4] = *(const float4*)&As[buf][kk][ty * 4 + 64];
            *(float4*)&bf[0] = *(const float4*)&Bs[buf][kk][tx * 4];
            *(float4*)&bf[4] = *(const float4*)&Bs[buf][kk][tx * 4 + 64];
#pragma unroll
            for (int i = 0; i < 8; i++)
#pragma unroll
                for (int j = 0; j < 8; j++)
                    acc[i][j] = fmaf(af[i], bf[j], acc[i][j]);
        }

        // ---- head flush every 4 k-steps ----
        if ((ks & 3) == 3) {
            const int h = ks >> 2;
            if (PHASE == 0) {
#pragma unroll
                for (int i = 0; i < 8; i++) {
                    float s = 0.0f;
#pragma unroll
                    for (int j = 0; j < 8; j++) { s += fast_exp_s(acc[i][j]); acc[i][j] = 0.0f; }
#pragma unroll
                    for (int o = 1; o < 16; o <<= 1) s += __shfl_xor_sync(0xffffffffu, s, o);
                    if (tx == 0) {
                        int r = (i < 4) ? (ty * 4 + i) : (64 + ty * 4 + (i - 4));
                        zsm[h][r] = s;
                    }
                }
            } else {
                const float* zp = zinv + ((size_t)z * NH + h) * SEQ + m0;
#pragma unroll
                for (int i = 0; i < 8; i++) {
                    int r = (i < 4) ? (ty * 4 + i) : (64 + ty * 4 + (i - 4));
                    float zi = zp[r];
#pragma unroll
                    for (int j = 0; j < 8; j++) {
                        ew[i][j] = fmaf(fast_exp_s(acc[i][j]), zi, ew[i][j]);
                        acc[i][j] = 0.0f;
                    }
                }
            }
        }

        if (more) {
            const int nb = buf ^ 1;
            As[nb][aK4+0][aRow] = a0.x; As[nb][aK4+1][aRow] = a0.y;
            As[nb][aK4+2][aRow] = a0.z; As[nb][aK4+3][aRow] = a0.w;
            As[nb][aK4+0][aRow+64] = a1.x; As[nb][aK4+1][aRow+64] = a1.y;
            As[nb][aK4+2][aRow+64] = a1.z; As[nb][aK4+3][aRow+64] = a1.w;
            Bs[nb][aK4+0][aRow] = b0.x; Bs[nb][aK4+1][aRow] = b0.y;
            Bs[nb][aK4+2][aRow] = b0.z; Bs[nb][aK4+3][aRow] = b0.w;
            Bs[nb][aK4+0][aRow+64] = b1.x; Bs[nb][aK4+1][aRow+64] = b1.y;
            Bs[nb][aK4+2][aRow+64] = b1.z; Bs[nb][aK4+3][aRow+64] = b1.w;
            __syncthreads();
            buf = nb;
        }
    }

    if (PHASE == 0) {
        __syncthreads();
        // zpart[((b*NJT + jt)*NH + h)*SEQ + m0 + r]
        float* zo = zpart + ((size_t)(z * NJT + jt) * NH) * SEQ;
        for (int idx = tid; idx < NH * 128; idx += 256) {
            int h = idx >> 7, r = idx & 127;
            zo[(size_t)h * SEQ + m0 + r] = zsm[h][r];
        }
    } else {
        float* C = ewm + (size_t)z * SEQ * SEQ;
#pragma unroll
        for (int ih = 0; ih < 2; ih++) {
#pragma unroll
            for (int i = 0; i < 4; i++) {
                const int m = m0 + ih * 64 + ty * 4 + i;
                const int ia = ih * 4 + i;
                *(float4*)&C[(size_t)m * SEQ + n0 + tx * 4     ] = *(float4*)&ew[ia][0];
                *(float4*)&C[(size_t)m * SEQ + n0 + 64 + tx * 4] = *(float4*)&ew[ia][4];
            }
        }
        // neighbor counts
#pragma unroll
        for (int i = 0; i < 8; i++) {
            int c = 0;
#pragma unroll
            for (int j = 0; j < 8; j++) c += (ew[i][j] > 0.1f) ? 1 : 0;
#pragma unroll
            for (int o = 1; o < 16; o <<= 1) c += __shfl_xor_sync(0xffffffffu, c, o);
            if (tx == 0) {
                int r = (i < 4) ? (ty * 4 + i) : (64 + ty * 4 + (i - 4));
                atomicAdd(&cnt[z * SEQ + m0 + r], c);
            }
        }
    }
}

// ---- Z partial reduce: zinv = 1/(8*sum_jt zpart) --------------------------------
__global__ void zred_kernel(const float* __restrict__ zpart, float* __restrict__ zinv)
{
    int t = blockIdx.x * blockDim.x + threadIdx.x;   // B*NH*SEQ
    if (t < BATCH * NH * SEQ) {
        int b = t / (NH * SEQ);
        int rem = t - b * NH * SEQ;
        float s = 0.0f;
#pragma unroll
        for (int jt = 0; jt < NJT; jt++)
            s += zpart[(size_t)(b * NJT + jt) * NH * SEQ + rem];
        zinv[t] = 1.0f / (8.0f * s);
    }
}

// ---- counts -> invnn ------------------------------------------------------------
__global__ void invnn_kernel(const int* __restrict__ cnt, float* __restrict__ invnn)
{
    int i = blockIdx.x * blockDim.x + threadIdx.x;
    if (i < BS) {
        float f = (float)cnt[i];
        invnn[i] = 1.0f / fmaxf(f, 1.0f);
    }
}

// ======= fused dual aggregation: msg = ewm@V + diag(invnn)·(mask(ewm)@X) =========
__global__ __launch_bounds__(256)
void dual_agg(const float* __restrict__ EW, const float* __restrict__ V,
              const float* __restrict__ X, const float* __restrict__ invnn,
              float* __restrict__ MSG)
{
    __shared__ __align__(16) float As [2][8][132];
    __shared__ __align__(16) float Bvs[2][8][132];
    __shared__ __align__(16) float Bxs[2][8][132];

    const int z = blockIdx.z;
    const float* A  = EW + (long long)z * SEQ * SEQ;
    const float* Bv = V  + (long long)z * SEQ * EMB;
    const float* Bx = X  + (long long)z * SEQ * EMB;
    float* C = MSG + (long long)z * SEQ * EMB;

    const int m0 = blockIdx.y * 128;
    const int n0 = blockIdx.x * 128;
    const int tid = threadIdx.x;
    const int tx = tid & 15;
    const int ty = tid >> 4;

    const int aRow = tid >> 1;
    const int aK4  = (tid & 1) << 2;
    const int bK   = tid >> 5;
    const int bN4  = (tid & 31) << 2;

    float4 a0, bv0, bx0;

    a0  = *(const float4*)&A [(long long)(m0 + aRow) * SEQ + aK4];
    bv0 = *(const float4*)&Bv[(long long)bK * EMB + n0 + bN4];
    bx0 = *(const float4*)&Bx[(long long)bK * EMB + n0 + bN4];
    As[0][aK4+0][aRow] = a0.x; As[0][aK4+1][aRow] = a0.y;
    As[0][aK4+2][aRow] = a0.z; As[0][aK4+3][aRow] = a0.w;
    *(float4*)&Bvs[0][bK][bN4] = bv0;
    *(float4*)&Bxs[0][bK][bN4] = bx0;
    __syncthreads();

    float accv[8][8], accx[8][8];
#pragma unroll
    for (int i = 0; i < 8; i++)
#pragma unroll
        for (int j = 0; j < 8; j++) { accv[i][j] = 0.0f; accx[i][j] = 0.0f; }

    int buf = 0;
    for (int k0 = 0; k0 < SEQ; k0 += 8) {
        const int k1 = k0 + 8;
        const bool more = (k1 < SEQ);
        if (more) {
            a0  = *(const float4*)&A [(long long)(m0 + aRow) * SEQ + k1 + aK4];
            bv0 = *(const float4*)&Bv[(long long)(k1 + bK) * EMB + n0 + bN4];
            bx0 = *(const float4*)&Bx[(long long)(k1 + bK) * EMB + n0 + bN4];
        }

#pragma unroll
        for (int kk = 0; kk < 8; kk++) {
            float af[8], am[8], bv[8], bx[8];
            *(float4*)&af[0] = *(const float4*)&As[buf][kk][ty * 4];
            *(float4*)&af[4] = *(const float4*)&As[buf][kk][ty * 4 + 64];
            *(float4*)&bv[0] = *(const float4*)&Bvs[buf][kk][tx * 4];
            *(float4*)&bv[4] = *(const float4*)&Bvs[buf][kk][tx * 4 + 64];
            *(float4*)&bx[0] = *(const float4*)&Bxs[buf][kk][tx * 4];
            *(float4*)&bx[4] = *(const float4*)&Bxs[buf][kk][tx * 4 + 64];
#pragma unroll
            for (int i = 0; i < 8; i++) am[i] = (af[i] > 0.1f) ? af[i] : 0.0f;
#pragma unroll
            for (int i = 0; i < 8; i++)
#pragma unroll
                for (int j = 0; j < 8; j++) {
                    accv[i][j] = fmaf(af[i], bv[j], accv[i][j]);
                    accx[i][j] = fmaf(am[i], bx[j], accx[i][j]);
                }
        }

        if (more) {
            const int nb = buf ^ 1;
            As[nb][aK4+0][aRow] = a0.x; As[nb][aK4+1][aRow] = a0.y;
            As[nb][aK4+2][aRow] = a0.z; As[nb][aK4+3][aRow] = a0.w;
            *(float4*)&Bvs[nb][bK][bN4] = bv0;
            *(float4*)&Bxs[nb][bK][bN4] = bx0;
            __syncthreads();
            buf = nb;
        }
    }

#pragma unroll
    for (int ih = 0; ih < 2; ih++) {
#pragma unroll
        for (int i = 0; i < 4; i++) {
            const int m = m0 + ih * 64 + ty * 4 + i;
            const int ia = ih * 4 + i;
            const float inv = invnn[z * SEQ + m];
            float o0[4], o1[4];
#pragma unroll
            for (int j = 0; j < 4; j++) {
                o0[j] = fmaf(accx[ia][j],     inv, accv[ia][j]);
                o1[j] = fmaf(accx[ia][j + 4], inv, accv[ia][j + 4]);
            }
            *(float4*)&C[(long long)m * EMB + n0 + tx * 4     ] = *(float4*)&o0[0];
            *(float4*)&C[(long long)m * EMB + n0 + 64 + tx * 4] = *(float4*)&o1[0];
        }
    }
}

// ---------------- effective MLP bias: edge_features == 1/S analytically ----------
__global__ void bm1eff_kernel(const float* __restrict__ Wm1,
                              const float* __restrict__ bm1,
                              float* __restrict__ out)
{
    int e = blockIdx.x * blockDim.x + threadIdx.x;
    if (e < EMB) {
        float s = 0.0f;
#pragma unroll
        for (int h = 0; h < NH; h++) s += Wm1[(long long)e * W1LD + EMB + h];
        out[e] = bm1[e] + s * (1.0f / (float)SEQ);
    }
}

// ---------------- driver ---------------------------------------------------------
extern "C" void kernel_launch(void* const* d_in, const int* in_sizes, int n_in,
                              void* d_out, int out_size)
{
    const float* x   = (const float*)d_in[0];
    const float* Wq  = (const float*)d_in[1];
    const float* bq  = (const float*)d_in[2];
    const float* Wk  = (const float*)d_in[3];
    const float* bk  = (const float*)d_in[4];
    const float* Wv  = (const float*)d_in[5];
    const float* bv  = (const float*)d_in[6];
    const float* Wm1 = (const float*)d_in[7];
    const float* bm1 = (const float*)d_in[8];
    const float* Wm2 = (const float*)d_in[9];
    const float* bm2 = (const float*)d_in[10];
    const float* Wo  = (const float*)d_in[11];
    const float* bo  = (const float*)d_in[12];
    float* out = (float*)d_out;

    float *q, *k, *v, *ewm, *zpart, *zinv, *invnn, *mid, *pre, *msg, *bm1eff;
    int *cnt;
    cudaGetSymbolAddress((void**)&q,      g_q);
    cudaGetSymbolAddress((void**)&k,      g_k);
    cudaGetSymbolAddress((void**)&v,      g_v);
    cudaGetSymbolAddress((void**)&ewm,    g_ewm);
    cudaGetSymbolAddress((void**)&zpart,  g_zpart);
    cudaGetSymbolAddress((void**)&zinv,   g_zinv);
    cudaGetSymbolAddress((void**)&cnt,    g_cnt);
    cudaGetSymbolAddress((void**)&invnn,  g_invnn);
    cudaGetSymbolAddress((void**)&mid,    g_mid);
    cudaGetSymbolAddress((void**)&pre,    g_pre);
    cudaGetSymbolAddress((void**)&msg,    g_msg);
    cudaGetSymbolAddress((void**)&bm1eff, g_bm1eff);

    bm1eff_kernel<<<1, 512>>>(Wm1, bm1, bm1eff);

    // fused QKV projections
    dim3 gQKV(3 * (EMB / 128), BS / 128, 1);
    qkv_gemm<<<gQKV, 256>>>(x, Wq, bq, Wk, bk, Wv, bv, q, k, v);

    // independent MLP branch (no deps on attention)
    dim3 gP(EMB / 128, BS / 128, 1);
    sgemm128<true, true><<<gP, 256>>>(x, Wm1, bm1eff, nullptr, mid, EMB, EMB, W1LD, EMB, 0, 0, 0, 1.0f);

    // phase 1: softmax normalizer partials (no score materialization)
    dim3 gS(NJT, SEQ / 128, BATCH);
    score_pass<0><<<gS, 256>>>(q, k, zpart, nullptr, nullptr, nullptr);
    zred_kernel<<<(BATCH * NH * SEQ + 255) / 256, 256>>>(zpart, zinv);

    // phase 2: ewm + neighbor counts
    cudaMemsetAsync(cnt, 0, BS * sizeof(int));
    score_pass<1><<<gS, 256>>>(q, k, nullptr, zinv, ewm, cnt);
    invnn_kernel<<<(BS + 255) / 256, 256>>>(cnt, invnn);

    // fused dual aggregation
    dim3 gA(EMB / 128, SEQ / 128, BATCH);
    dual_agg<<<gA, 256>>>(ewm, v, x, invnn, msg);

    // pre = mid @ Wm2^T + bm2 + msg ; out = pre @ Wo^T + bo
    sgemm128<true, false><<<gP, 256>>>(mid, Wm2, bm2, msg,     pre, EMB, EMB, EMB, EMB, 0, 0, 0, 1.0f);
    sgemm128<true, false><<<gP, 256>>>(pre, Wo,  bo,  nullptr, out, EMB, EMB, EMB, EMB, 0, 0, 0, 1.0f);
}

// round 17
// speedup vs baseline: 1.1205x; 1.1205x over previous
#include <cuda_runtime.h>
#include <math.h>

#define BATCH 2
#define SEQ   2048
#define EMB   512
#define NH    8
#define HD    64
#define BS    (BATCH*SEQ)      /* 4096 */
#define W1LD  (EMB+NH)         /* 520  */
#define NJT   (SEQ/128)        /* 16 j-tiles */

// ---------------- scratch (device globals; no allocation allowed) ----------------
__device__ float g_q[BS*EMB];
__device__ float g_k[BS*EMB];
__device__ float g_v[BS*EMB];
__device__ float g_exp[(size_t)BATCH*NH*SEQ*SEQ];      // exp(score*scale), 256 MB
__device__ float g_ewm[(size_t)BATCH*SEQ*SEQ];         // mean edge weights (32 MB)
__device__ float g_zpart[(size_t)BATCH*NJT*NH*SEQ];    // per-jtile softmax partials
__device__ float g_zinv[(size_t)BATCH*NH*SEQ];         // 1/(8*Z)
__device__ float g_invnn[BS];
__device__ float g_mid[BS*EMB];
__device__ float g_pre[BS*EMB];
__device__ float g_msg[BS*EMB];
__device__ float g_bm1eff[EMB];

// ---------------- fast exp of (0.125*x) on the FMA pipe --------------------------
__device__ __forceinline__ float fast_exp_s(float x) {
    float t  = x * (1.4426950408889634f * 0.125f);   // scale folded into log2(e)
    t = fmaxf(t, -115.0f);
    float fi = floorf(t + 0.5f);
    float f  = t - fi;
    float u  = f * 0.6931471805599453f;
    float p = 1.0f + u*(1.0f + u*(0.5f + u*(0.16666667f + u*(0.041666667f + u*0.0083333333f))));
    return __int_as_float(((int)fi + 127) << 23) * p;
}

// ================= shared GEMM body: 128x128 tile, BK=16, split 4+4 microtile ====
template<bool TB, bool GELU>
__device__ __forceinline__ void gemm_body(
    const float* __restrict__ A, const float* __restrict__ B,
    const float* __restrict__ bias, const float* __restrict__ res,
    float* __restrict__ C, int K, int lda, int ldb, int ldc,
    int m0, int n0, float alpha)
{
    __shared__ __align__(16) float As[2][16][132];
    __shared__ __align__(16) float Bs[2][16][132];

    const int tid = threadIdx.x;
    const int tx = tid & 15;
    const int ty = tid >> 4;

    const int aRow = tid >> 2;
    const int aK4  = (tid & 3) << 2;
    const int bK   = tid >> 5;
    const int bN4  = (tid & 31) << 2;

    float4 a0, a1, b0, b1;

    {
        const float* Ap = A + (long long)m0 * lda;
        a0 = *(const float4*)&Ap[(long long)aRow        * lda + aK4];
        a1 = *(const float4*)&Ap[(long long)(aRow + 64) * lda + aK4];
        if (TB) {
            const float* Bp = B + (long long)n0 * ldb;
            b0 = *(const float4*)&Bp[(long long)aRow        * ldb + aK4];
            b1 = *(const float4*)&Bp[(long long)(aRow + 64) * ldb + aK4];
        } else {
            const float* Bp = B + n0;
            b0 = *(const float4*)&Bp[(long long)bK       * ldb + bN4];
            b1 = *(const float4*)&Bp[(long long)(bK + 8) * ldb + bN4];
        }
    }
    {
        As[0][aK4+0][aRow] = a0.x; As[0][aK4+1][aRow] = a0.y;
        As[0][aK4+2][aRow] = a0.z; As[0][aK4+3][aRow] = a0.w;
        As[0][aK4+0][aRow+64] = a1.x; As[0][aK4+1][aRow+64] = a1.y;
        As[0][aK4+2][aRow+64] = a1.z; As[0][aK4+3][aRow+64] = a1.w;
        if (TB) {
            Bs[0][aK4+0][aRow] = b0.x; Bs[0][aK4+1][aRow] = b0.y;
            Bs[0][aK4+2][aRow] = b0.z; Bs[0][aK4+3][aRow] = b0.w;
            Bs[0][aK4+0][aRow+64] = b1.x; Bs[0][aK4+1][aRow+64] = b1.y;
            Bs[0][aK4+2][aRow+64] = b1.z; Bs[0][aK4+3][aRow+64] = b1.w;
        } else {
            *(float4*)&Bs[0][bK    ][bN4] = b0;
            *(float4*)&Bs[0][bK + 8][bN4] = b1;
        }
    }
    __syncthreads();

    float acc[8][8];
#pragma unroll
    for (int i = 0; i < 8; i++)
#pragma unroll
        for (int j = 0; j < 8; j++) acc[i][j] = 0.0f;

    int buf = 0;
    for (int k0 = 0; k0 < K; k0 += 16) {
        const int k1 = k0 + 16;
        const bool more = (k1 < K);
        if (more) {
            const float* Ap = A + (long long)m0 * lda + k1;
            a0 = *(const float4*)&Ap[(long long)aRow        * lda + aK4];
            a1 = *(const float4*)&Ap[(long long)(aRow + 64) * lda + aK4];
            if (TB) {
                const float* Bp = B + (long long)n0 * ldb + k1;
                b0 = *(const float4*)&Bp[(long long)aRow        * ldb + aK4];
                b1 = *(const float4*)&Bp[(long long)(aRow + 64) * ldb + aK4];
            } else {
                const float* Bp = B + (long long)k1 * ldb + n0;
                b0 = *(const float4*)&Bp[(long long)bK       * ldb + bN4];
                b1 = *(const float4*)&Bp[(long long)(bK + 8) * ldb + bN4];
            }
        }

#pragma unroll
        for (int kk = 0; kk < 16; kk++) {
            float af[8], bf[8];
            *(float4*)&af[0] = *(const float4*)&As[buf][kk][ty * 4];
            *(float4*)&af[4] = *(const float4*)&As[buf][kk][ty * 4 + 64];
            *(float4*)&bf[0] = *(const float4*)&Bs[buf][kk][tx * 4];
            *(float4*)&bf[4] = *(const float4*)&Bs[buf][kk][tx * 4 + 64];
#pragma unroll
            for (int i = 0; i < 8; i++)
#pragma unroll
                for (int j = 0; j < 8; j++)
                    acc[i][j] = fmaf(af[i], bf[j], acc[i][j]);
        }

        if (more) {
            const int nb = buf ^ 1;
            As[nb][aK4+0][aRow] = a0.x; As[nb][aK4+1][aRow] = a0.y;
            As[nb][aK4+2][aRow] = a0.z; As[nb][aK4+3][aRow] = a0.w;
            As[nb][aK4+0][aRow+64] = a1.x; As[nb][aK4+1][aRow+64] = a1.y;
            As[nb][aK4+2][aRow+64] = a1.z; As[nb][aK4+3][aRow+64] = a1.w;
            if (TB) {
                Bs[nb][aK4+0][aRow] = b0.x; Bs[nb][aK4+1][aRow] = b0.y;
                Bs[nb][aK4+2][aRow] = b0.z; Bs[nb][aK4+3][aRow] = b0.w;
                Bs[nb][aK4+0][aRow+64] = b1.x; Bs[nb][aK4+1][aRow+64] = b1.y;
                Bs[nb][aK4+2][aRow+64] = b1.z; Bs[nb][aK4+3][aRow+64] = b1.w;
            } else {
                *(float4*)&Bs[nb][bK    ][bN4] = b0;
                *(float4*)&Bs[nb][bK + 8][bN4] = b1;
            }
            __syncthreads();
            buf = nb;
        }
    }

    float bb0[4], bb1[4];
#pragma unroll
    for (int j = 0; j < 4; j++) {
        bb0[j] = bias ? bias[n0 + tx * 4 + j]      : 0.0f;
        bb1[j] = bias ? bias[n0 + 64 + tx * 4 + j] : 0.0f;
    }

#pragma unroll
    for (int ih = 0; ih < 2; ih++) {
#pragma unroll
        for (int i = 0; i < 4; i++) {
            const long long m = m0 + ih * 64 + ty * 4 + i;
            const int ia = ih * 4 + i;
            float o0[4], o1[4];
#pragma unroll
            for (int j = 0; j < 4; j++) {
                float v0 = fmaf(acc[ia][j],     alpha, bb0[j]);
                float v1 = fmaf(acc[ia][j + 4], alpha, bb1[j]);
                if (GELU) {
                    v0 = 0.5f * v0 * (1.0f + erff(v0 * 0.70710678118654752f));
                    v1 = 0.5f * v1 * (1.0f + erff(v1 * 0.70710678118654752f));
                }
                o0[j] = v0; o1[j] = v1;
            }
            if (res) {
                float4 r0 = *(const float4*)&res[m * ldc + n0 + tx * 4];
                float4 r1 = *(const float4*)&res[m * ldc + n0 + 64 + tx * 4];
                o0[0] += r0.x; o0[1] += r0.y; o0[2] += r0.z; o0[3] += r0.w;
                o1[0] += r1.x; o1[1] += r1.y; o1[2] += r1.z; o1[3] += r1.w;
            }
            *(float4*)&C[m * ldc + n0 + tx * 4     ] = *(float4*)&o0[0];
            *(float4*)&C[m * ldc + n0 + 64 + tx * 4] = *(float4*)&o1[0];
        }
    }
}

template<bool TB, bool GELU>
__global__ __launch_bounds__(256)
void sgemm128(const float* __restrict__ A, const float* __restrict__ B,
              const float* __restrict__ bias, const float* __restrict__ res,
              float* __restrict__ C,
              int K, int lda, int ldb, int ldc,
              long long sA, long long sB, long long sC, float alpha)
{
    gemm_body<TB, GELU>(A + (long long)blockIdx.z * sA,
                        B + (long long)blockIdx.z * sB,
                        bias, res ? res + (long long)blockIdx.z * sC : nullptr,
                        C + (long long)blockIdx.z * sC,
                        K, lda, ldb, ldc,
                        blockIdx.y * 128, blockIdx.x * 128, alpha);
}

// ---- fused QKV ----
__global__ __launch_bounds__(256)
void qkv_gemm(const float* __restrict__ x,
              const float* __restrict__ Wq, const float* __restrict__ bq,
              const float* __restrict__ Wk, const float* __restrict__ bk,
              const float* __restrict__ Wv, const float* __restrict__ bv,
              float* __restrict__ q, float* __restrict__ k, float* __restrict__ v)
{
    const int seg = blockIdx.x >> 2;
    const float* W = (seg == 0) ? Wq : (seg == 1) ? Wk : Wv;
    const float* b = (seg == 0) ? bq : (seg == 1) ? bk : bv;
    float*     out = (seg == 0) ? q  : (seg == 1) ? k  : v;
    gemm_body<true, false>(x, W, b, nullptr, out,
                           EMB, EMB, EMB, EMB,
                           blockIdx.y * 128, (blockIdx.x & 3) * 128, 1.0f);
}

// ===== single score pass: q·k^T GEMM (K=512, per-head flush) -> exp store + Z ====
__global__ __launch_bounds__(256)
void score_z_kernel(const float* __restrict__ Q, const float* __restrict__ Km,
                    float* __restrict__ Ex, float* __restrict__ zpart)
{
    __shared__ __align__(16) float As[2][16][132];
    __shared__ __align__(16) float Bs[2][16][132];
    __shared__ float zsm[NH][128];

    const int z  = blockIdx.z;
    const int jt = blockIdx.x;
    const float* A = Q  + (long long)z * SEQ * EMB;
    const float* B = Km + (long long)z * SEQ * EMB;
    const int m0 = blockIdx.y * 128;
    const int n0 = jt * 128;

    const int tid = threadIdx.x;
    const int tx = tid & 15;
    const int ty = tid >> 4;
    const int aRow = tid >> 2;
    const int aK4  = (tid & 3) << 2;

    float4 a0, a1, b0, b1;
    {
        const float* Ap = A + (long long)m0 * EMB;
        const float* Bp = B + (long long)n0 * EMB;
        a0 = *(const float4*)&Ap[(long long)aRow        * EMB + aK4];
        a1 = *(const float4*)&Ap[(long long)(aRow + 64) * EMB + aK4];
        b0 = *(const float4*)&Bp[(long long)aRow        * EMB + aK4];
        b1 = *(const float4*)&Bp[(long long)(aRow + 64) * EMB + aK4];
        As[0][aK4+0][aRow] = a0.x; As[0][aK4+1][aRow] = a0.y;
        As[0][aK4+2][aRow] = a0.z; As[0][aK4+3][aRow] = a0.w;
        As[0][aK4+0][aRow+64] = a1.x; As[0][aK4+1][aRow+64] = a1.y;
        As[0][aK4+2][aRow+64] = a1.z; As[0][aK4+3][aRow+64] = a1.w;
        Bs[0][aK4+0][aRow] = b0.x; Bs[0][aK4+1][aRow] = b0.y;
        Bs[0][aK4+2][aRow] = b0.z; Bs[0][aK4+3][aRow] = b0.w;
        Bs[0][aK4+0][aRow+64] = b1.x; Bs[0][aK4+1][aRow+64] = b1.y;
        Bs[0][aK4+2][aRow+64] = b1.z; Bs[0][aK4+3][aRow+64] = b1.w;
    }
    __syncthreads();

    float acc[8][8];
#pragma unroll
    for (int i = 0; i < 8; i++)
#pragma unroll
        for (int j = 0; j < 8; j++) acc[i][j] = 0.0f;

    int buf = 0;
    for (int ks = 0; ks < 32; ks++) {
        const int k1 = (ks + 1) * 16;
        const bool more = (k1 < EMB);
        if (more) {
            const float* Ap = A + (long long)m0 * EMB + k1;
            const float* Bp = B + (long long)n0 * EMB + k1;
            a0 = *(const float4*)&Ap[(long long)aRow        * EMB + aK4];
            a1 = *(const float4*)&Ap[(long long)(aRow + 64) * EMB + aK4];
            b0 = *(const float4*)&Bp[(long long)aRow        * EMB + aK4];
            b1 = *(const float4*)&Bp[(long long)(aRow + 64) * EMB + aK4];
        }

#pragma unroll
        for (int kk = 0; kk < 16; kk++) {
            float af[8], bf[8];
            *(float4*)&af[0] = *(const float4*)&As[buf][kk][ty * 4];
            *(float4*)&af[4] = *(const float4*)&As[buf][kk][ty * 4 + 64];
            *(float4*)&bf[0] = *(const float4*)&Bs[buf][kk][tx * 4];
            *(float4*)&bf[4] = *(const float4*)&Bs[buf][kk][tx * 4 + 64];
#pragma unroll
            for (int i = 0; i < 8; i++)
#pragma unroll
                for (int j = 0; j < 8; j++)
                    acc[i][j] = fmaf(af[i], bf[j], acc[i][j]);
        }

        // ---- head flush every 4 k-steps: exp -> store plane + Z row-sum ----
        if ((ks & 3) == 3) {
            const int h = ks >> 2;
            float* Ep = Ex + (size_t)(z * NH + h) * SEQ * SEQ;
#pragma unroll
            for (int i = 0; i < 8; i++) {
                float ev[8];
#pragma unroll
                for (int j = 0; j < 8; j++) { ev[j] = fast_exp_s(acc[i][j]); acc[i][j] = 0.0f; }
                const int r = (i < 4) ? (ty * 4 + i) : (64 + ty * 4 + (i - 4));
                *(float4*)&Ep[(size_t)(m0 + r) * SEQ + n0 + tx * 4     ] = *(float4*)&ev[0];
                *(float4*)&Ep[(size_t)(m0 + r) * SEQ + n0 + 64 + tx * 4] = *(float4*)&ev[4];
                float s = ev[0]+ev[1]+ev[2]+ev[3]+ev[4]+ev[5]+ev[6]+ev[7];
#pragma unroll
                for (int o = 1; o < 16; o <<= 1) s += __shfl_xor_sync(0xffffffffu, s, o);
                if (tx == 0) zsm[h][r] = s;
            }
        }

        if (more) {
            const int nb = buf ^ 1;
            As[nb][aK4+0][aRow] = a0.x; As[nb][aK4+1][aRow] = a0.y;
            As[nb][aK4+2][aRow] = a0.z; As[nb][aK4+3][aRow] = a0.w;
            As[nb][aK4+0][aRow+64] = a1.x; As[nb][aK4+1][aRow+64] = a1.y;
            As[nb][aK4+2][aRow+64] = a1.z; As[nb][aK4+3][aRow+64] = a1.w;
            Bs[nb][aK4+0][aRow] = b0.x; Bs[nb][aK4+1][aRow] = b0.y;
            Bs[nb][aK4+2][aRow] = b0.z; Bs[nb][aK4+3][aRow] = b0.w;
            Bs[nb][aK4+0][aRow+64] = b1.x; Bs[nb][aK4+1][aRow+64] = b1.y;
            Bs[nb][aK4+2][aRow+64] = b1.z; Bs[nb][aK4+3][aRow+64] = b1.w;
            __syncthreads();
            buf = nb;
        }
    }

    __syncthreads();
    float* zo = zpart + ((size_t)(z * NJT + jt) * NH) * SEQ;
    for (int idx = tid; idx < NH * 128; idx += 256) {
        int h = idx >> 7, r = idx & 127;
        zo[(size_t)h * SEQ + m0 + r] = zsm[h][r];
    }
}

// ---- Z partial reduce: zinv = 1/(8*sum_jt zpart) --------------------------------
__global__ void zred_kernel(const float* __restrict__ zpart, float* __restrict__ zinv)
{
    int t = blockIdx.x * blockDim.x + threadIdx.x;
    if (t < BATCH * NH * SEQ) {
        int b = t / (NH * SEQ);
        int rem = t - b * NH * SEQ;
        float s = 0.0f;
#pragma unroll
        for (int jt = 0; jt < NJT; jt++)
            s += zpart[(size_t)(b * NJT + jt) * NH * SEQ + rem];
        zinv[t] = 1.0f / (8.0f * s);
    }
}

// ---- ewm from stored exps: one block per (b,i) row; also emits invnn ------------
__global__ __launch_bounds__(256)
void ewm_kernel(const float* __restrict__ Ex, const float* __restrict__ zinv,
                float* __restrict__ ewm, float* __restrict__ invnn)
{
    __shared__ int wcnt[8];
    const int bi = blockIdx.x;
    const int b  = bi >> 11;          // /SEQ
    const int i  = bi & (SEQ - 1);
    const int tid = threadIdx.x;

    const size_t plane = (size_t)SEQ * SEQ;
    const float* Eb = Ex + ((size_t)b * NH * SEQ + i) * SEQ;

    float zi[NH];
#pragma unroll
    for (int h = 0; h < NH; h++) zi[h] = zinv[(b * NH + h) * SEQ + i];

    float* Crow = ewm + ((size_t)b * SEQ + i) * SEQ;
    int cnt = 0;

#pragma unroll
    for (int it = 0; it < 2; it++) {
        const int j = (it * 256 + tid) * 4;
        float4 acc = make_float4(0.f, 0.f, 0.f, 0.f);
#pragma unroll
        for (int h = 0; h < NH; h++) {
            float4 e = *(const float4*)&Eb[(size_t)h * plane + j];
            acc.x = fmaf(e.x, zi[h], acc.x);
            acc.y = fmaf(e.y, zi[h], acc.y);
            acc.z = fmaf(e.z, zi[h], acc.z);
            acc.w = fmaf(e.w, zi[h], acc.w);
        }
        *(float4*)&Crow[j] = acc;
        cnt += (acc.x > 0.1f) + (acc.y > 0.1f) + (acc.z > 0.1f) + (acc.w > 0.1f);
    }

#pragma unroll
    for (int o = 16; o > 0; o >>= 1) cnt += __shfl_xor_sync(0xffffffffu, cnt, o);
    if ((tid & 31) == 0) wcnt[tid >> 5] = cnt;
    __syncthreads();
    if (tid == 0) {
        int c = 0;
#pragma unroll
        for (int w = 0; w < 8; w++) c += wcnt[w];
        invnn[bi] = 1.0f / fmaxf((float)c, 1.0f);
    }
}

// ======= fused dual aggregation: msg = ewm@V + diag(invnn)·(mask(ewm)@X) =========
__global__ __launch_bounds__(256)
void dual_agg(const float* __restrict__ EW, const float* __restrict__ V,
              const float* __restrict__ X, const float* __restrict__ invnn,
              float* __restrict__ MSG)
{
    __shared__ __align__(16) float As [2][8][132];
    __shared__ __align__(16) float Bvs[2][8][132];
    __shared__ __align__(16) float Bxs[2][8][132];

    const int z = blockIdx.z;
    const float* A  = EW + (long long)z * SEQ * SEQ;
    const float* Bv = V  + (long long)z * SEQ * EMB;
    const float* Bx = X  + (long long)z * SEQ * EMB;
    float* C = MSG + (long long)z * SEQ * EMB;

    const int m0 = blockIdx.y * 128;
    const int n0 = blockIdx.x * 128;
    const int tid = threadIdx.x;
    const int tx = tid & 15;
    const int ty = tid >> 4;

    const int aRow = tid >> 1;
    const int aK4  = (tid & 1) << 2;
    const int bK   = tid >> 5;
    const int bN4  = (tid & 31) << 2;

    float4 a0, bv0, bx0;

    a0  = *(const float4*)&A [(long long)(m0 + aRow) * SEQ + aK4];
    bv0 = *(const float4*)&Bv[(long long)bK * EMB + n0 + bN4];
    bx0 = *(const float4*)&Bx[(long long)bK * EMB + n0 + bN4];
    As[0][aK4+0][aRow] = a0.x; As[0][aK4+1][aRow] = a0.y;
    As[0][aK4+2][aRow] = a0.z; As[0][aK4+3][aRow] = a0.w;
    *(float4*)&Bvs[0][bK][bN4] = bv0;
    *(float4*)&Bxs[0][bK][bN4] = bx0;
    __syncthreads();

    float accv[8][8], accx[8][8];
#pragma unroll
    for (int i = 0; i < 8; i++)
#pragma unroll
        for (int j = 0; j < 8; j++) { accv[i][j] = 0.0f; accx[i][j] = 0.0f; }

    int buf = 0;
    for (int k0 = 0; k0 < SEQ; k0 += 8) {
        const int k1 = k0 + 8;
        const bool more = (k1 < SEQ);
        if (more) {
            a0  = *(const float4*)&A [(long long)(m0 + aRow) * SEQ + k1 + aK4];
            bv0 = *(const float4*)&Bv[(long long)(k1 + bK) * EMB + n0 + bN4];
            bx0 = *(const float4*)&Bx[(long long)(k1 + bK) * EMB + n0 + bN4];
        }

#pragma unroll
        for (int kk = 0; kk < 8; kk++) {
            float af[8], am[8], bv[8], bx[8];
            *(float4*)&af[0] = *(const float4*)&As[buf][kk][ty * 4];
            *(float4*)&af[4] = *(const float4*)&As[buf][kk][ty * 4 + 64];
            *(float4*)&bv[0] = *(const float4*)&Bvs[buf][kk][tx * 4];
            *(float4*)&bv[4] = *(const float4*)&Bvs[buf][kk][tx * 4 + 64];
            *(float4*)&bx[0] = *(const float4*)&Bxs[buf][kk][tx * 4];
            *(float4*)&bx[4] = *(const float4*)&Bxs[buf][kk][tx * 4 + 64];
#pragma unroll
            for (int i = 0; i < 8; i++) am[i] = (af[i] > 0.1f) ? af[i] : 0.0f;
#pragma unroll
            for (int i = 0; i < 8; i++)
#pragma unroll
                for (int j = 0; j < 8; j++) {
                    accv[i][j] = fmaf(af[i], bv[j], accv[i][j]);
                    accx[i][j] = fmaf(am[i], bx[j], accx[i][j]);
                }
        }

        if (more) {
            const int nb = buf ^ 1;
            As[nb][aK4+0][aRow] = a0.x; As[nb][aK4+1][aRow] = a0.y;
            As[nb][aK4+2][aRow] = a0.z; As[nb][aK4+3][aRow] = a0.w;
            *(float4*)&Bvs[nb][bK][bN4] = bv0;
            *(float4*)&Bxs[nb][bK][bN4] = bx0;
            __syncthreads();
            buf = nb;
        }
    }

#pragma unroll
    for (int ih = 0; ih < 2; ih++) {
#pragma unroll
        for (int i = 0; i < 4; i++) {
            const int m = m0 + ih * 64 + ty * 4 + i;
            const int ia = ih * 4 + i;
            const float inv = invnn[z * SEQ + m];
            float o0[4], o1[4];
#pragma unroll
            for (int j = 0; j < 4; j++) {
                o0[j] = fmaf(accx[ia][j],     inv, accv[ia][j]);
                o1[j] = fmaf(accx[ia][j + 4], inv, accv[ia][j + 4]);
            }
            *(float4*)&C[(long long)m * EMB + n0 + tx * 4     ] = *(float4*)&o0[0];
            *(float4*)&C[(long long)m * EMB + n0 + 64 + tx * 4] = *(float4*)&o1[0];
        }
    }
}

// ---------------- effective MLP bias: edge_features == 1/S analytically ----------
__global__ void bm1eff_kernel(const float* __restrict__ Wm1,
                              const float* __restrict__ bm1,
                              float* __restrict__ out)
{
    int e = blockIdx.x * blockDim.x + threadIdx.x;
    if (e < EMB) {
        float s = 0.0f;
#pragma unroll
        for (int h = 0; h < NH; h++) s += Wm1[(long long)e * W1LD + EMB + h];
        out[e] = bm1[e] + s * (1.0f / (float)SEQ);
    }
}

// ---------------- driver ---------------------------------------------------------
extern "C" void kernel_launch(void* const* d_in, const int* in_sizes, int n_in,
                              void* d_out, int out_size)
{
    const float* x   = (const float*)d_in[0];
    const float* Wq  = (const float*)d_in[1];
    const float* bq  = (const float*)d_in[2];
    const float* Wk  = (const float*)d_in[3];
    const float* bk  = (const float*)d_in[4];
    const float* Wv  = (const float*)d_in[5];
    const float* bv  = (const float*)d_in[6];
    const float* Wm1 = (const float*)d_in[7];
    const float* bm1 = (const float*)d_in[8];
    const float* Wm2 = (const float*)d_in[9];
    const float* bm2 = (const float*)d_in[10];
    const float* Wo  = (const float*)d_in[11];
    const float* bo  = (const float*)d_in[12];
    float* out = (float*)d_out;

    float *q, *k, *v, *ex, *ewm, *zpart, *zinv, *invnn, *mid, *pre, *msg, *bm1eff;
    cudaGetSymbolAddress((void**)&q,      g_q);
    cudaGetSymbolAddress((void**)&k,      g_k);
    cudaGetSymbolAddress((void**)&v,      g_v);
    cudaGetSymbolAddress((void**)&ex,     g_exp);
    cudaGetSymbolAddress((void**)&ewm,    g_ewm);
    cudaGetSymbolAddress((void**)&zpart,  g_zpart);
    cudaGetSymbolAddress((void**)&zinv,   g_zinv);
    cudaGetSymbolAddress((void**)&invnn,  g_invnn);
    cudaGetSymbolAddress((void**)&mid,    g_mid);
    cudaGetSymbolAddress((void**)&pre,    g_pre);
    cudaGetSymbolAddress((void**)&msg,    g_msg);
    cudaGetSymbolAddress((void**)&bm1eff, g_bm1eff);

    bm1eff_kernel<<<1, 512>>>(Wm1, bm1, bm1eff);

    // fused QKV projections
    dim3 gQKV(3 * (EMB / 128), BS / 128, 1);
    qkv_gemm<<<gQKV, 256>>>(x, Wq, bq, Wk, bk, Wv, bv, q, k, v);

    // independent MLP branch
    dim3 gP(EMB / 128, BS / 128, 1);
    sgemm128<true, true><<<gP, 256>>>(x, Wm1, bm1eff, nullptr, mid, EMB, EMB, W1LD, EMB, 0, 0, 0, 1.0f);

    // single score pass: exps stored + Z partials
    dim3 gS(NJT, SEQ / 128, BATCH);
    score_z_kernel<<<gS, 256>>>(q, k, ex, zpart);
    zred_kernel<<<(BATCH * NH * SEQ + 255) / 256, 256>>>(zpart, zinv);

    // normalize + head-mean + neighbor counts (streaming)
    ewm_kernel<<<BS, 256>>>(ex, zinv, ewm, invnn);

    // fused dual aggregation
    dim3 gA(EMB / 128, SEQ / 128, BATCH);
    dual_agg<<<gA, 256>>>(ewm, v, x, invnn, msg);

    // pre = mid @ Wm2^T + bm2 + msg ; out = pre @ Wo^T + bo
    sgemm128<true, false><<<gP, 256>>>(mid, Wm2, bm2, msg,     pre, EMB, EMB, EMB, EMB, 0, 0, 0, 1.0f);
    sgemm128<true, false><<<gP, 256>>>(pre, Wo,  bo,  nullptr, out, EMB, EMB, EMB, EMB, 0, 0, 0, 1.0f);
}